// round 2
// baseline (speedup 1.0000x reference)
#include <cuda_runtime.h>
#include <math.h>

// Problem constants
#define BB 2
#define NN 8192
#define EE 768
#define HH 12
#define DD 64
#define MTOT (BB*NN)        // 16384

// Scratch (device globals: allocation-guard safe)
__device__ float g_Q[BB*NN*EE];
__device__ float g_K[BB*NN*EE];
__device__ float g_V[BB*NN*EE];
__device__ float g_O4[BB*NN*EE];
__device__ float g_part[32*BB*EE];
__device__ float g_inv[BB*EE];

// ---------------------------------------------------------------------------
// Zero the attention scatter buffer (positions not gathered must be 0)
// ---------------------------------------------------------------------------
__global__ void zero_O4_kernel() {
    size_t i = (size_t)blockIdx.x * blockDim.x + threadIdx.x;
    ((float4*)g_O4)[i] = make_float4(0.f, 0.f, 0.f, 0.f);
}

// ---------------------------------------------------------------------------
// C[m,n] = alpha * ( sum_k A[m,k]*(colscale? colscale[b(m),k]:1) * W[n,k] + bias[n] )
// M=16384, N=K=768.  128x128x16 tiles, 256 threads, 8x8 microtile.
// ---------------------------------------------------------------------------
__global__ __launch_bounds__(256) void gemm768_kernel(
    const float* __restrict__ A, const float* __restrict__ W,
    const float* __restrict__ bias, const float* __restrict__ colscale,
    float alpha, float* __restrict__ C)
{
    __shared__ float As[16*132];   // [k][m], padded ld=132
    __shared__ float Bs[16*132];   // [k][n]
    const int tid = threadIdx.x;
    const int tx = tid & 15, ty = tid >> 4;
    const int m0 = blockIdx.y * 128;
    const int n0 = blockIdx.x * 128;

    float acc[8][8];
#pragma unroll
    for (int i = 0; i < 8; ++i)
#pragma unroll
        for (int j = 0; j < 8; ++j) acc[i][j] = 0.f;

    const int lrow = tid >> 2;   // 0..63 (second pass +64)
    const int k4   = tid & 3;    // float4 index along k (16 wide)

    for (int kb = 0; kb < 768; kb += 16) {
#pragma unroll
        for (int l = 0; l < 2; ++l) {
            int r = lrow + l*64;
            float4 av = *(const float4*)(A + (size_t)(m0 + r)*768 + kb + k4*4);
            if (colscale) {
                float4 cs = *(const float4*)(colscale + ((m0 + r) >> 13)*768 + kb + k4*4);
                av.x *= cs.x; av.y *= cs.y; av.z *= cs.z; av.w *= cs.w;
            }
            As[(k4*4+0)*132 + r] = av.x;
            As[(k4*4+1)*132 + r] = av.y;
            As[(k4*4+2)*132 + r] = av.z;
            As[(k4*4+3)*132 + r] = av.w;
            float4 wv = *(const float4*)(W + (size_t)(n0 + r)*768 + kb + k4*4);
            Bs[(k4*4+0)*132 + r] = wv.x;
            Bs[(k4*4+1)*132 + r] = wv.y;
            Bs[(k4*4+2)*132 + r] = wv.z;
            Bs[(k4*4+3)*132 + r] = wv.w;
        }
        __syncthreads();
#pragma unroll
        for (int k = 0; k < 16; ++k) {
            float4 a0 = *(const float4*)(As + k*132 + ty*8);
            float4 a1 = *(const float4*)(As + k*132 + ty*8 + 4);
            float4 b0 = *(const float4*)(Bs + k*132 + tx*8);
            float4 b1 = *(const float4*)(Bs + k*132 + tx*8 + 4);
            float a[8] = {a0.x,a0.y,a0.z,a0.w,a1.x,a1.y,a1.z,a1.w};
            float bb[8] = {b0.x,b0.y,b0.z,b0.w,b1.x,b1.y,b1.z,b1.w};
#pragma unroll
            for (int i = 0; i < 8; ++i)
#pragma unroll
                for (int j = 0; j < 8; ++j)
                    acc[i][j] += a[i]*bb[j];
        }
        __syncthreads();
    }
    float4 bias0 = *(const float4*)(bias + n0 + tx*8);
    float4 bias1 = *(const float4*)(bias + n0 + tx*8 + 4);
#pragma unroll
    for (int i = 0; i < 8; ++i) {
        float4 o0, o1;
        o0.x = (acc[i][0] + bias0.x)*alpha; o0.y = (acc[i][1] + bias0.y)*alpha;
        o0.z = (acc[i][2] + bias0.z)*alpha; o0.w = (acc[i][3] + bias0.w)*alpha;
        o1.x = (acc[i][4] + bias1.x)*alpha; o1.y = (acc[i][5] + bias1.y)*alpha;
        o1.z = (acc[i][6] + bias1.z)*alpha; o1.w = (acc[i][7] + bias1.w)*alpha;
        float* cp = C + (size_t)(m0 + ty*8 + i)*768 + n0 + tx*8;
        *(float4*)cp       = o0;
        *(float4*)(cp + 4) = o1;
    }
}

// ---------------------------------------------------------------------------
// Dilated flash attention.
// grid: x = q-tile (16 tiles of 128 over L=2048), y = instance (56 total)
//  instances: grp0 (r=1,s=2048): b(2) x seg(4) x head(4) = 32
//             grp1 (r=2,s=4096): b(2) x seg(2) x head(4) = 16
//             grp2 (r=4,s=8192): b(2) x seg(1) x head(4) = 8
// token(p) = seg*s + off + p*r, off = grp; head = grp*4 + hl.
// Q already pre-scaled by 1/8 at projection.
// ---------------------------------------------------------------------------
#define ATTN_SMEM_FLOATS (64*132 + 64*68 + 64*64 + 64*132)
#define ATTN_SMEM_BYTES  (ATTN_SMEM_FLOATS*4)

__global__ __launch_bounds__(256, 2) void attn_kernel()
{
    extern __shared__ float sm[];
    float* Qst = sm;                      // [d=64][m=128] ld 132
    float* Kst = sm + 64*132;             // [d=64][n=64]  ld 68
    float* Vs  = Kst + 64*68;             // [k=64][d=64]  ld 64
    float* Pst = Vs + 64*64;              // [k=64][m=128] ld 132

    const int tid = threadIdx.x;
    const int tx = tid & 15, ty = tid >> 4;

    const int inst = blockIdx.y;
    int grp, b, seg, hl;
    if (inst < 32)      { grp = 0; b = inst >> 4;        seg = (inst >> 2) & 3; hl = inst & 3; }
    else if (inst < 48) { int r = inst - 32; grp = 1; b = r >> 3; seg = (r >> 2) & 1; hl = r & 3; }
    else                { int r = inst - 48; grp = 2; b = r >> 2; seg = 0;            hl = r & 3; }
    const int rate = 1 << grp;
    const int slen = 2048 << grp;
    const int off  = grp;            // 0%1=0, 1%2=1, 2%4=2
    const int head = grp*4 + hl;
    const int q0   = blockIdx.x * 128;

    const size_t base = (size_t)b*NN*EE + (size_t)(seg*slen + off)*EE + head*DD;
    const int stride = rate * EE;

    // Load Q tile (128 rows x 64 d), transposed into Qst[d][m]
#pragma unroll
    for (int l = 0; l < 8; ++l) {
        int idx = tid + l*256;
        int row = idx >> 4;        // 0..127
        int c4  = idx & 15;        // float4 along d
        float4 v = *(const float4*)(g_Q + base + (size_t)(q0 + row)*stride + c4*4);
        Qst[(c4*4+0)*132 + row] = v.x;
        Qst[(c4*4+1)*132 + row] = v.y;
        Qst[(c4*4+2)*132 + row] = v.z;
        Qst[(c4*4+3)*132 + row] = v.w;
    }

    float m_i[8], l_i[8], O[8][4];
#pragma unroll
    for (int i = 0; i < 8; ++i) {
        m_i[i] = -1e30f; l_i[i] = 0.f;
#pragma unroll
        for (int j = 0; j < 4; ++j) O[i][j] = 0.f;
    }

    for (int kt = 0; kt < 32; ++kt) {
        const int k0 = kt * 64;
        __syncthreads();  // prior-iter reads of Kst/Vs/Pst done; Qst visible (first iter)
        // Load K (transposed) and V (natural)
#pragma unroll
        for (int l = 0; l < 4; ++l) {
            int idx = tid + l*256;
            int row = idx >> 4;    // 0..63
            int c4  = idx & 15;
            float4 kv = *(const float4*)(g_K + base + (size_t)(k0 + row)*stride + c4*4);
            Kst[(c4*4+0)*68 + row] = kv.x;
            Kst[(c4*4+1)*68 + row] = kv.y;
            Kst[(c4*4+2)*68 + row] = kv.z;
            Kst[(c4*4+3)*68 + row] = kv.w;
            float4 vv = *(const float4*)(g_V + base + (size_t)(k0 + row)*stride + c4*4);
            *(float4*)(Vs + row*64 + c4*4) = vv;
        }
        __syncthreads();

        // S = Q * K^T  (8 rows x 4 cols per thread)
        float S[8][4];
#pragma unroll
        for (int i = 0; i < 8; ++i)
#pragma unroll
            for (int j = 0; j < 4; ++j) S[i][j] = 0.f;
#pragma unroll 8
        for (int k = 0; k < 64; ++k) {
            float4 a0 = *(const float4*)(Qst + k*132 + ty*8);
            float4 a1 = *(const float4*)(Qst + k*132 + ty*8 + 4);
            float4 bv = *(const float4*)(Kst + k*68 + tx*4);
            float a[8] = {a0.x,a0.y,a0.z,a0.w,a1.x,a1.y,a1.z,a1.w};
#pragma unroll
            for (int i = 0; i < 8; ++i) {
                S[i][0] += a[i]*bv.x;
                S[i][1] += a[i]*bv.y;
                S[i][2] += a[i]*bv.z;
                S[i][3] += a[i]*bv.w;
            }
        }

        // Online softmax; write P transposed to Pst[k][m]
#pragma unroll
        for (int i = 0; i < 8; ++i) {
            float mx = fmaxf(fmaxf(S[i][0], S[i][1]), fmaxf(S[i][2], S[i][3]));
#pragma unroll
            for (int w = 8; w > 0; w >>= 1)
                mx = fmaxf(mx, __shfl_xor_sync(0xffffffffu, mx, w));
            float mnew = fmaxf(m_i[i], mx);
            float corr = __expf(m_i[i] - mnew);
            m_i[i] = mnew;
            float rs = 0.f;
#pragma unroll
            for (int j = 0; j < 4; ++j) {
                float p = __expf(S[i][j] - mnew);
                S[i][j] = p;
                rs += p;
            }
#pragma unroll
            for (int w = 8; w > 0; w >>= 1)
                rs += __shfl_xor_sync(0xffffffffu, rs, w);
            l_i[i] = l_i[i]*corr + rs;
#pragma unroll
            for (int j = 0; j < 4; ++j) {
                O[i][j] *= corr;
                Pst[(tx*4+j)*132 + ty*8 + i] = S[i][j];
            }
        }
        __syncthreads();

        // O += P * V
#pragma unroll 8
        for (int k = 0; k < 64; ++k) {
            float4 p0 = *(const float4*)(Pst + k*132 + ty*8);
            float4 p1 = *(const float4*)(Pst + k*132 + ty*8 + 4);
            float4 vv = *(const float4*)(Vs + k*64 + tx*4);
            float p[8] = {p0.x,p0.y,p0.z,p0.w,p1.x,p1.y,p1.z,p1.w};
#pragma unroll
            for (int i = 0; i < 8; ++i) {
                O[i][0] += p[i]*vv.x;
                O[i][1] += p[i]*vv.y;
                O[i][2] += p[i]*vv.z;
                O[i][3] += p[i]*vv.w;
            }
        }
    }

    // Epilogue: normalize rows and scatter to g_O4
#pragma unroll
    for (int i = 0; i < 8; ++i) {
        float inv = 1.0f / l_i[i];
        float4 o;
        o.x = O[i][0]*inv; o.y = O[i][1]*inv; o.z = O[i][2]*inv; o.w = O[i][3]*inv;
        int p = q0 + ty*8 + i;
        *(float4*)(g_O4 + base + (size_t)p*stride + tx*4) = o;
    }
}

// ---------------------------------------------------------------------------
// denom[b,c] = sum_n O4[b,n,c] over n=8192; two-phase deterministic reduction
// ---------------------------------------------------------------------------
__global__ void colsum_part_kernel()
{
    int chunk = blockIdx.x;               // 0..31  (256 n-rows each)
    int bc    = blockIdx.y;               // 0..5
    int b  = bc / 3;
    int c  = (bc % 3)*256 + threadIdx.x;  // 0..767
    const float* p = g_O4 + ((size_t)b*NN + chunk*256)*EE + c;
    float s = 0.f;
#pragma unroll 8
    for (int n = 0; n < 256; ++n) {
        s += *p;
        p += EE;
    }
    g_part[chunk*(BB*EE) + b*EE + c] = s;
}

__global__ void colsum_reduce_kernel()
{
    int i = blockIdx.x*256 + threadIdx.x;  // 0..1535
    float s = 0.f;
#pragma unroll
    for (int ch = 0; ch < 32; ++ch) s += g_part[ch*(BB*EE) + i];
    g_inv[i] = 1.0f / s;
}

// ---------------------------------------------------------------------------
extern "C" void kernel_launch(void* const* d_in, const int* in_sizes, int n_in,
                              void* d_out, int out_size)
{
    const float* query = (const float*)d_in[0];
    const float* key   = (const float*)d_in[1];
    const float* value = (const float*)d_in[2];
    const float* Wq = (const float*)d_in[3];
    const float* bq = (const float*)d_in[4];
    const float* Wk = (const float*)d_in[5];
    const float* bk = (const float*)d_in[6];
    const float* Wv = (const float*)d_in[7];
    const float* bv = (const float*)d_in[8];
    const float* Wo = (const float*)d_in[9];
    const float* bo = (const float*)d_in[10];
    float* out = (float*)d_out;

    float *pQ, *pK, *pV, *pO4, *pInv;
    cudaGetSymbolAddress((void**)&pQ,   g_Q);
    cudaGetSymbolAddress((void**)&pK,   g_K);
    cudaGetSymbolAddress((void**)&pV,   g_V);
    cudaGetSymbolAddress((void**)&pO4,  g_O4);
    cudaGetSymbolAddress((void**)&pInv, g_inv);

    cudaFuncSetAttribute(attn_kernel,
                         cudaFuncAttributeMaxDynamicSharedMemorySize,
                         ATTN_SMEM_BYTES);

    // 1. zero scatter buffer
    zero_O4_kernel<<<12288, 256>>>();

    // 2. projections (Q pre-scaled by softmax scale 1/sqrt(64) = 0.125,
    //    applied AFTER bias add — matches scores*(1/8) with q including bias)
    dim3 gg(6, 128);
    gemm768_kernel<<<gg, 256>>>(query, Wq, bq, nullptr, 0.125f, pQ);
    gemm768_kernel<<<gg, 256>>>(key,   Wk, bk, nullptr, 1.0f,   pK);
    gemm768_kernel<<<gg, 256>>>(value, Wv, bv, nullptr, 1.0f,   pV);

    // 3. dilated attention (56 instances x 16 q-tiles)
    attn_kernel<<<dim3(16, 56), 256, ATTN_SMEM_BYTES>>>();

    // 4. sequence-sum normalization factors (deterministic 2-phase)
    colsum_part_kernel<<<dim3(32, 6), 256>>>();
    colsum_reduce_kernel<<<6, 256>>>();

    // 5. output projection with fused per-(b,col) 1/denom scaling
    gemm768_kernel<<<gg, 256>>>(pO4, Wo, bo, pInv, 1.0f, out);
}